// round 13
// baseline (speedup 1.0000x reference)
#include <cuda_runtime.h>
#include <cuda_bf16.h>
#include <cstdint>

// -------------------------------------------------------------------------
// CoralFocalLoss_MultiTask — software-pipelined grid-stride body.
//
// Evidence through R11: seven body variants all plateau at 25-29us with
// issue ~65% and DRAM ~52% — latency-exposed, not pipe-bound. Cause: each
// iteration batches its 10 LDGs then runs a long dependent compute chain
// with no loads in flight. Fix: double-buffer — prefetch iteration
// (i+stride)'s 13 values before computing iteration i, so every warp keeps
// ~10 loads outstanding during compute.
//
// Body math (measured-best lean base-2 form, rel_err 4.4e-6):
//   z = x*(±log2e); t = ex2(z); a = 1+t; u = 1/a (bit trick + 2 Newton);
//   loss = [alpha*ln2] * u^2 * (lg2(a) - z), alpha*ln2 pre-folded in FSEL.
//   2 MUFU/logit (floor, per R6); no LUT (R9: smem conflicts lose 12us).
//
// __launch_bounds__(256, 6): caps regs at 42 (13 prefetch regs on top of
// the ~30-reg base), occupancy 75% (48 warps/SM) — R3 showed 35% occ loses,
// R2 showed 82% wins; 75% with doubled MLP should net positive.
//
// Structure: main kernel -> fixed-order per-block partials -> tiny separate
// finalize kernel (best-measured config).
// -------------------------------------------------------------------------

#define NBLOCKS 1184
#define NTHREADS 256

__device__ float g_partials[NBLOCKS * 3];

__device__ __forceinline__ float ex2a(float x) {
    float r; asm("ex2.approx.f32 %0, %1;" : "=f"(r) : "f"(x)); return r;
}
__device__ __forceinline__ float lg2a(float x) {
    float r; asm("lg2.approx.f32 %0, %1;" : "=f"(r) : "f"(x)); return r;
}

#define L2E_P  1.44269504088896340736f   //  log2(e)
#define L2E_N (-1.44269504088896340736f) // -log2(e)
#define A1T    0.17328679513998632735f   // 0.25 * ln2
#define A0T    0.51986038541995898205f   // 0.75 * ln2

// returns [alpha*ln2] * u^2 * (lg2 a - z); caller accumulates
__device__ __forceinline__ float coral_term(float x, bool tm) {
    float sc = tm ? L2E_P : L2E_N;                             // FSEL
    float al = tm ? A1T   : A0T;                               // FSEL
    float z  = x * sc;                                         // FMUL
    float t  = ex2a(z);                                        // MUFU
    float a  = 1.0f + t;                                       // FADD
    float u  = __int_as_float(0x7EF311C3 - __float_as_int(a)); // IADD
    u = u * (2.0f - a * u);                                    // FFMA + FMUL
    u = u * (2.0f - a * u);                                    // FFMA + FMUL
    float g  = lg2a(a);                                        // MUFU
    float p  = g - z;                                          // FADD
    return al * ((u * u) * p);                                 // 3 FMUL
}

__global__ void __launch_bounds__(NTHREADS, 6)
coral_main_kernel(const float* __restrict__ kl_logits,
                  const float* __restrict__ jsnm_logits,
                  const float* __restrict__ jsnl_logits,
                  const float* __restrict__ class_weights,
                  const int*   __restrict__ kl_t,
                  const int*   __restrict__ jsnm_t,
                  const int*   __restrict__ jsnl_t,
                  int n)
{
    __shared__ float s_w[5];
    if (threadIdx.x < 5) s_w[threadIdx.x] = class_weights[threadIdx.x];
    __syncthreads();

    float sum_kl = 0.0f, sum_m = 0.0f, sum_l = 0.0f;

    const int stride = gridDim.x * blockDim.x;
    int i = blockIdx.x * blockDim.x + threadIdx.x;

    if (i < n) {
        // ---- prologue: load iteration 0 ----
        int kt = kl_t[i];
        int mt = jsnm_t[i];
        int lt = jsnl_t[i];
        float4 q = reinterpret_cast<const float4*>(kl_logits)[i];
        const float* pm = jsnm_logits + 3 * (size_t)i;
        float m0 = pm[0], m1 = pm[1], m2 = pm[2];
        const float* pl = jsnl_logits + 3 * (size_t)i;
        float l0 = pl[0], l1 = pl[1], l2 = pl[2];

        while (true) {
            int  inext = i + stride;
            bool more  = inext < n;
            int  ip    = more ? inext : i;   // clamp: final prefetch re-reads i (L1 hit, discarded)

            // ---- prefetch iteration i+stride (13 values, in flight during compute) ----
            int kt2 = kl_t[ip];
            int mt2 = jsnm_t[ip];
            int lt2 = jsnl_t[ip];
            float4 q2 = reinterpret_cast<const float4*>(kl_logits)[ip];
            const float* pm2 = jsnm_logits + 3 * (size_t)ip;
            float nm0 = pm2[0], nm1 = pm2[1], nm2 = pm2[2];
            const float* pl2 = jsnl_logits + 3 * (size_t)ip;
            float nl0 = pl2[0], nl1 = pl2[1], nl2 = pl2[2];

            // ---- compute iteration i ----
            float w = s_w[kt];

            float rk = coral_term(q.x, 0 < kt)
                     + coral_term(q.y, 1 < kt)
                     + coral_term(q.z, 2 < kt)
                     + coral_term(q.w, 3 < kt);
            sum_kl = fmaf(w, rk, sum_kl);

            float rm = coral_term(m0, 0 < mt)
                     + coral_term(m1, 1 < mt)
                     + coral_term(m2, 2 < mt);
            sum_m = fmaf(w, rm, sum_m);

            float rl = coral_term(l0, 0 < lt)
                     + coral_term(l1, 1 < lt)
                     + coral_term(l2, 2 < lt);
            sum_l = fmaf(w, rl, sum_l);

            if (!more) break;

            // ---- rotate buffers ----
            i  = inext;
            kt = kt2; mt = mt2; lt = lt2;
            q  = q2;
            m0 = nm0; m1 = nm1; m2 = nm2;
            l0 = nl0; l1 = nl1; l2 = nl2;
        }
    }

    // -------- deterministic block reduction --------
    const unsigned FULL = 0xFFFFFFFFu;
    #pragma unroll
    for (int o = 16; o > 0; o >>= 1) {
        sum_kl += __shfl_down_sync(FULL, sum_kl, o);
        sum_m  += __shfl_down_sync(FULL, sum_m,  o);
        sum_l  += __shfl_down_sync(FULL, sum_l,  o);
    }

    __shared__ float s_red[3][NTHREADS / 32];
    int wid = threadIdx.x >> 5;
    int lid = threadIdx.x & 31;
    if (lid == 0) {
        s_red[0][wid] = sum_kl;
        s_red[1][wid] = sum_m;
        s_red[2][wid] = sum_l;
    }
    __syncthreads();

    if (threadIdx.x == 0) {
        float v0 = 0.0f, v1 = 0.0f, v2 = 0.0f;
        #pragma unroll
        for (int i2 = 0; i2 < NTHREADS / 32; i2++) {
            v0 += s_red[0][i2];
            v1 += s_red[1][i2];
            v2 += s_red[2][i2];
        }
        g_partials[blockIdx.x * 3 + 0] = v0;
        g_partials[blockIdx.x * 3 + 1] = v1;
        g_partials[blockIdx.x * 3 + 2] = v2;
    }
}

__global__ void __launch_bounds__(NTHREADS)
coral_finalize_kernel(float* __restrict__ out, int nblocks, int n)
{
    float v0 = 0.0f, v1 = 0.0f, v2 = 0.0f;
    for (int i = threadIdx.x; i < nblocks; i += NTHREADS) {
        v0 += g_partials[i * 3 + 0];
        v1 += g_partials[i * 3 + 1];
        v2 += g_partials[i * 3 + 2];
    }
    const unsigned FULL = 0xFFFFFFFFu;
    #pragma unroll
    for (int o = 16; o > 0; o >>= 1) {
        v0 += __shfl_down_sync(FULL, v0, o);
        v1 += __shfl_down_sync(FULL, v1, o);
        v2 += __shfl_down_sync(FULL, v2, o);
    }
    __shared__ float s_red[3][NTHREADS / 32];
    int wid = threadIdx.x >> 5;
    int lid = threadIdx.x & 31;
    if (lid == 0) {
        s_red[0][wid] = v0;
        s_red[1][wid] = v1;
        s_red[2][wid] = v2;
    }
    __syncthreads();
    if (threadIdx.x == 0) {
        float t0 = 0.0f, t1 = 0.0f, t2 = 0.0f;
        #pragma unroll
        for (int i = 0; i < NTHREADS / 32; i++) {
            t0 += s_red[0][i];
            t1 += s_red[1][i];
            t2 += s_red[2][i];
        }
        float fn = (float)n;
        float l_kl   = t0 / (4.0f * fn);
        float l_jsnm = t1 / (3.0f * fn);
        float l_jsnl = t2 / (3.0f * fn);
        out[0] = (l_kl + l_jsnm + l_jsnl) * (1.0f / 3.0f);
        out[1] = l_kl;
        out[2] = l_jsnm;
        out[3] = l_jsnl;
    }
}

extern "C" void kernel_launch(void* const* d_in, const int* in_sizes, int n_in,
                              void* d_out, int out_size)
{
    const float* kl_logits     = (const float*)d_in[0];
    const float* jsnm_logits   = (const float*)d_in[1];
    const float* jsnl_logits   = (const float*)d_in[2];
    const float* class_weights = (const float*)d_in[3];
    const int*   kl_t          = (const int*)d_in[4];
    const int*   jsnm_t        = (const int*)d_in[5];
    const int*   jsnl_t        = (const int*)d_in[6];

    int n = in_sizes[4];  // N samples (kl_t element count)

    coral_main_kernel<<<NBLOCKS, NTHREADS>>>(
        kl_logits, jsnm_logits, jsnl_logits, class_weights,
        kl_t, jsnm_t, jsnl_t, n);

    coral_finalize_kernel<<<1, NTHREADS>>>((float*)d_out, NBLOCKS, n);
}

// round 16
// speedup vs baseline: 1.1097x; 1.1097x over previous
#include <cuda_runtime.h>
#include <cuda_bf16.h>
#include <cstdint>

// -------------------------------------------------------------------------
// CoralFocalLoss_MultiTask — converged kernel (best-measured: R1, 25.44us).
//
// Per element (logit x, binary coral target tm):
//   loss = alpha(tm) * h(y),  y = tm ? x : -x,  alpha = tm ? 0.25 : 0.75
//   h(y) = sigmoid(-y)^2 * softplus(-y) = u^2 * (s - y)
//      t = e^y, u = 1/(1+t), s = log(1+t)
// Row loss scaled by class_weights[kl_t]. Outputs are means.
//
// 2 MUFU (EX2, LG2) per logit; reciprocal on the FMA pipe via bit trick +
// 2 Newton steps (~6e-6 one-sided rel err, vs 1e-3 tolerance).
//
// Convergence evidence (9 variants, R1-R13): rcp.approx (+3.4us), f32x2
// packing (+1.3), smem LUT (+11.8), 4x unroll (+2.7), base-2 lean (+1.4),
// software pipelining (+2.1), fused finalize (+1.2) — all lost or tied.
// The kernel sits at a balanced MUFU(9.4us)/issue(~15us)/DRAM(~13us) bind;
// shifting work between these resources is measured to be a wash.
// -------------------------------------------------------------------------

#define NBLOCKS 1184
#define NTHREADS 256

__device__ float g_partials[NBLOCKS * 3];

__device__ __forceinline__ float fast_rcp(float a) {
    // valid for a in [1, ~1e6]; here a = 1 + e^y >= 1
    float u = __int_as_float(0x7EF311C3 - __float_as_int(a));
    u = u * (2.0f - a * u);
    u = u * (2.0f - a * u);
    return u;
}

__device__ __forceinline__ float coral_term(float x, bool tm) {
    float y     = tm ? x : -x;
    float alpha = tm ? 0.25f : 0.75f;
    float t = __expf(y);           // EX2 (+mul)
    float a = 1.0f + t;
    float u = fast_rcp(a);         // FMA pipe
    float s = __logf(a);           // LG2 (+mul)
    return alpha * (u * u) * (s - y);
}

__global__ void __launch_bounds__(NTHREADS)
coral_main_kernel(const float* __restrict__ kl_logits,
                  const float* __restrict__ jsnm_logits,
                  const float* __restrict__ jsnl_logits,
                  const float* __restrict__ class_weights,
                  const int*   __restrict__ kl_t,
                  const int*   __restrict__ jsnm_t,
                  const int*   __restrict__ jsnl_t,
                  int n)
{
    __shared__ float s_w[5];
    if (threadIdx.x < 5) s_w[threadIdx.x] = class_weights[threadIdx.x];
    __syncthreads();

    float sum_kl = 0.0f, sum_m = 0.0f, sum_l = 0.0f;

    int stride = gridDim.x * blockDim.x;
    for (int i = blockIdx.x * blockDim.x + threadIdx.x; i < n; i += stride) {
        int kt = kl_t[i];
        int mt = jsnm_t[i];
        int lt = jsnl_t[i];
        float w = s_w[kt];

        float4 q = reinterpret_cast<const float4*>(kl_logits)[i];
        float rk = coral_term(q.x, 0 < kt)
                 + coral_term(q.y, 1 < kt)
                 + coral_term(q.z, 2 < kt)
                 + coral_term(q.w, 3 < kt);
        sum_kl += w * rk;

        const float* pm = jsnm_logits + 3 * (size_t)i;
        float rm = coral_term(pm[0], 0 < mt)
                 + coral_term(pm[1], 1 < mt)
                 + coral_term(pm[2], 2 < mt);
        sum_m += w * rm;

        const float* pl = jsnl_logits + 3 * (size_t)i;
        float rl = coral_term(pl[0], 0 < lt)
                 + coral_term(pl[1], 1 < lt)
                 + coral_term(pl[2], 2 < lt);
        sum_l += w * rl;
    }

    // deterministic block reduction: warp shuffle, then shared across warps
    const unsigned FULL = 0xFFFFFFFFu;
    #pragma unroll
    for (int o = 16; o > 0; o >>= 1) {
        sum_kl += __shfl_down_sync(FULL, sum_kl, o);
        sum_m  += __shfl_down_sync(FULL, sum_m,  o);
        sum_l  += __shfl_down_sync(FULL, sum_l,  o);
    }

    __shared__ float s_red[3][NTHREADS / 32];
    int wid = threadIdx.x >> 5;
    int lid = threadIdx.x & 31;
    if (lid == 0) {
        s_red[0][wid] = sum_kl;
        s_red[1][wid] = sum_m;
        s_red[2][wid] = sum_l;
    }
    __syncthreads();

    if (wid == 0) {
        float v0 = (lid < NTHREADS / 32) ? s_red[0][lid] : 0.0f;
        float v1 = (lid < NTHREADS / 32) ? s_red[1][lid] : 0.0f;
        float v2 = (lid < NTHREADS / 32) ? s_red[2][lid] : 0.0f;
        #pragma unroll
        for (int o = 4; o > 0; o >>= 1) {
            v0 += __shfl_down_sync(FULL, v0, o);
            v1 += __shfl_down_sync(FULL, v1, o);
            v2 += __shfl_down_sync(FULL, v2, o);
        }
        if (lid == 0) {
            g_partials[blockIdx.x * 3 + 0] = v0;
            g_partials[blockIdx.x * 3 + 1] = v1;
            g_partials[blockIdx.x * 3 + 2] = v2;
        }
    }
}

__global__ void __launch_bounds__(NTHREADS)
coral_finalize_kernel(float* __restrict__ out, int nblocks, int n)
{
    float v0 = 0.0f, v1 = 0.0f, v2 = 0.0f;
    for (int i = threadIdx.x; i < nblocks; i += NTHREADS) {
        v0 += g_partials[i * 3 + 0];
        v1 += g_partials[i * 3 + 1];
        v2 += g_partials[i * 3 + 2];
    }
    const unsigned FULL = 0xFFFFFFFFu;
    #pragma unroll
    for (int o = 16; o > 0; o >>= 1) {
        v0 += __shfl_down_sync(FULL, v0, o);
        v1 += __shfl_down_sync(FULL, v1, o);
        v2 += __shfl_down_sync(FULL, v2, o);
    }
    __shared__ float s_red[3][NTHREADS / 32];
    int wid = threadIdx.x >> 5;
    int lid = threadIdx.x & 31;
    if (lid == 0) {
        s_red[0][wid] = v0;
        s_red[1][wid] = v1;
        s_red[2][wid] = v2;
    }
    __syncthreads();
    if (threadIdx.x == 0) {
        float t0 = 0.0f, t1 = 0.0f, t2 = 0.0f;
        #pragma unroll
        for (int i = 0; i < NTHREADS / 32; i++) {
            t0 += s_red[0][i];
            t1 += s_red[1][i];
            t2 += s_red[2][i];
        }
        float l_kl   = t0 / (4.0f * (float)n);
        float l_jsnm = t1 / (3.0f * (float)n);
        float l_jsnl = t2 / (3.0f * (float)n);
        float total  = (l_kl + l_jsnm + l_jsnl) * (1.0f / 3.0f);
        out[0] = total;
        out[1] = l_kl;
        out[2] = l_jsnm;
        out[3] = l_jsnl;
    }
}

extern "C" void kernel_launch(void* const* d_in, const int* in_sizes, int n_in,
                              void* d_out, int out_size)
{
    const float* kl_logits     = (const float*)d_in[0];
    const float* jsnm_logits   = (const float*)d_in[1];
    const float* jsnl_logits   = (const float*)d_in[2];
    const float* class_weights = (const float*)d_in[3];
    const int*   kl_t          = (const int*)d_in[4];
    const int*   jsnm_t        = (const int*)d_in[5];
    const int*   jsnl_t        = (const int*)d_in[6];

    int n = in_sizes[4];  // N samples (kl_t element count)

    coral_main_kernel<<<NBLOCKS, NTHREADS>>>(
        kl_logits, jsnm_logits, jsnl_logits, class_weights,
        kl_t, jsnm_t, jsnl_t, n);

    coral_finalize_kernel<<<1, NTHREADS>>>((float*)d_out, NBLOCKS, n);
}